// round 3
// baseline (speedup 1.0000x reference)
#include <cuda_runtime.h>
#include <cuda_bf16.h>

#define N_MAX 100000
#define E_MAX 1000000

// ---------------- device scratch ----------------
__device__ float  g_dinv[N_MAX];
__device__ int    g_src[E_MAX];
__device__ int    g_dst[E_MAX];
__device__ float  g_agg1[(size_t)N_MAX * 64];
__device__ float  g_h1  [(size_t)N_MAX * 128];
__device__ float  g_p2  [(size_t)N_MAX * 64];
__device__ float  g_agg2[(size_t)N_MAX * 64];
__device__ float2 g_pAB [N_MAX];

// ---------------- helpers ----------------
__device__ __forceinline__ void red_add_v4(float* p, float4 v) {
    asm volatile("red.global.add.v4.f32 [%0], {%1, %2, %3, %4};"
                 :: "l"(p), "f"(v.x), "f"(v.y), "f"(v.z), "f"(v.w)
                 : "memory");
}
__device__ __forceinline__ unsigned long long fma2(unsigned long long a,
                                                   unsigned long long b,
                                                   unsigned long long c) {
    unsigned long long d;
    asm("fma.rn.f32x2 %0, %1, %2, %3;" : "=l"(d) : "l"(a), "l"(b), "l"(c));
    return d;
}
__device__ __forceinline__ unsigned long long pack2(float x, float y) {
    unsigned long long d;
    asm("mov.b64 %0, {%1, %2};" : "=l"(d) : "f"(x), "f"(y));
    return d;
}
__device__ __forceinline__ void unpack2(unsigned long long v, float& lo, float& hi) {
    asm("mov.b64 {%0, %1}, %2;" : "=f"(lo), "=f"(hi) : "l"(v));
}

// ---------------- kernels ----------------

__global__ void __launch_bounds__(256) k_deg_init(int N) {
    int i = blockIdx.x * 256 + threadIdx.x;
    if (i < N) g_dinv[i] = 1.0f;
}

__global__ void __launch_bounds__(256) k_convert(const void* __restrict__ ei, int E) {
    long i = (long)blockIdx.x * 256 + threadIdx.x;
    if (i >= E) return;
    const unsigned long long* p64 = (const unsigned long long*)ei;
    bool is64 = true;
#pragma unroll
    for (int j = 0; j < 8; j++) is64 &= (p64[j] < (unsigned long long)N_MAX);
    int s, d;
    if (is64) {
        s = (int)p64[i];
        d = (int)p64[(long)E + i];
    } else {
        const int* p32 = (const int*)ei;
        s = p32[i];
        d = p32[(long)E + i];
    }
    g_src[i] = s;
    g_dst[i] = d;
    atomicAdd(&g_dinv[d], 1.0f);
}

// dinv = rsqrt(deg); agg1[i] = x[i]/deg[i]  (self-loop term)
__global__ void __launch_bounds__(256) k_selfinit(const float* __restrict__ x, int N) {
    int tid = threadIdx.x;
    int l = tid & 15;
    int row = blockIdx.x * 16 + (tid >> 4);
    if (row >= N) return;
    float dv = rsqrtf(g_dinv[row]);
    if (l == 0) g_dinv[row] = dv;
    float w = dv * dv;
    float4 v = __ldg((const float4*)x + (size_t)row * 16 + l);
    v.x *= w; v.y *= w; v.z *= w; v.w *= w;
    ((float4*)g_agg1)[(size_t)row * 16 + l] = v;
}

// Edge aggregation: 2 edges per thread-group for MLP.
__global__ void __launch_bounds__(256) k_agg(const float* __restrict__ xin, int E, int which) {
    int tid = threadIdx.x;
    int l = tid & 15;
    long e0 = (long)blockIdx.x * 32 + (tid >> 4);
    long e1 = e0 + 16;
    const float4* f4 = which ? (const float4*)g_p2 : (const float4*)xin;
    float*        ob = which ? g_agg2 : g_agg1;
    bool v0 = e0 < E, v1 = e1 < E;
    int s0 = 0, d0 = 0, s1 = 0, d1 = 0;
    if (v0) { s0 = g_src[e0]; d0 = g_dst[e0]; }
    if (v1) { s1 = g_src[e1]; d1 = g_dst[e1]; }
    float w0 = 0.f, w1 = 0.f;
    if (v0) w0 = g_dinv[s0] * g_dinv[d0];
    if (v1) w1 = g_dinv[s1] * g_dinv[d1];
    float4 x0 = make_float4(0, 0, 0, 0), x1 = x0;
    if (v0) x0 = __ldg(f4 + (size_t)s0 * 16 + l);
    if (v1) x1 = __ldg(f4 + (size_t)s1 * 16 + l);
    if (v0) {
        x0.x *= w0; x0.y *= w0; x0.z *= w0; x0.w *= w0;
        red_add_v4(ob + (size_t)d0 * 64 + l * 4, x0);
    }
    if (v1) {
        x1.x *= w1; x1.y *= w1; x1.z *= w1; x1.w *= w1;
        red_add_v4(ob + (size_t)d1 * 64 + l * 4, x1);
    }
}

// h1 = relu(agg1 @ W1 + b1)   [N,64]x[64,128]
// block = 64 rows x 128 cols; thread = 4 rows x 8 cols via f32x2.
__global__ void __launch_bounds__(256) k_gemm1(const float* __restrict__ W,
                                               const float* __restrict__ b, int N) {
    __shared__ float Ws[64 * 128];
    int tid = threadIdx.x;
    {
        const float4* wv = (const float4*)W;
        float4* sv = (float4*)Ws;
#pragma unroll
        for (int i = 0; i < 8; i++) sv[tid + 256 * i] = wv[tid + 256 * i];
    }
    __syncthreads();
    int tx = tid & 15, ty = tid >> 4;
    int c0 = tx * 8;
    long rowbase = (long)blockIdx.x * 64 + ty * 4;

    long rowc[4];
#pragma unroll
    for (int r = 0; r < 4; r++) {
        long rr = rowbase + r;
        rowc[r] = (rr < N) ? rr : (long)(N - 1);
    }
    unsigned long long acc[4][4];
    {
        float4 b0 = __ldg((const float4*)(b + c0));
        float4 b1 = __ldg((const float4*)(b + c0 + 4));
#pragma unroll
        for (int r = 0; r < 4; r++) {
            acc[r][0] = pack2(b0.x, b0.y);
            acc[r][1] = pack2(b0.z, b0.w);
            acc[r][2] = pack2(b1.x, b1.y);
            acc[r][3] = pack2(b1.z, b1.w);
        }
    }
#pragma unroll 4
    for (int k0 = 0; k0 < 64; k0 += 4) {
        float a_[4][4];
#pragma unroll
        for (int r = 0; r < 4; r++)
            *(float4*)a_[r] = __ldg((const float4*)(g_agg1 + (size_t)rowc[r] * 64 + k0));
#pragma unroll
        for (int kk = 0; kk < 4; kk++) {
            int k = k0 + kk;
            ulonglong2 wa = *(const ulonglong2*)&Ws[k * 128 + c0];
            ulonglong2 wb = *(const ulonglong2*)&Ws[k * 128 + c0 + 4];
#pragma unroll
            for (int r = 0; r < 4; r++) {
                unsigned long long Ar = pack2(a_[r][kk], a_[r][kk]);
                acc[r][0] = fma2(Ar, wa.x, acc[r][0]);
                acc[r][1] = fma2(Ar, wa.y, acc[r][1]);
                acc[r][2] = fma2(Ar, wb.x, acc[r][2]);
                acc[r][3] = fma2(Ar, wb.y, acc[r][3]);
            }
        }
    }
#pragma unroll
    for (int r = 0; r < 4; r++) {
        long row = rowbase + r;
        if (row >= N) break;
        float o[8];
        unpack2(acc[r][0], o[0], o[1]);
        unpack2(acc[r][1], o[2], o[3]);
        unpack2(acc[r][2], o[4], o[5]);
        unpack2(acc[r][3], o[6], o[7]);
#pragma unroll
        for (int j = 0; j < 8; j++) o[j] = fmaxf(o[j], 0.f);
        float* dst = g_h1 + (size_t)row * 128 + c0;
        *(float4*)dst       = make_float4(o[0], o[1], o[2], o[3]);
        *(float4*)(dst + 4) = make_float4(o[4], o[5], o[6], o[7]);
    }
}

// p2 = h1 @ W2 (no bias); agg2 = p2 * dinv^2 (fused self-loop init)
// block = 64 rows x 64 cols; thread = 4 rows x 4 cols.
__global__ void __launch_bounds__(256) k_gemm2(const float* __restrict__ W, int N) {
    __shared__ float Ws[128 * 64];
    int tid = threadIdx.x;
    {
        const float4* wv = (const float4*)W;
        float4* sv = (float4*)Ws;
#pragma unroll
        for (int i = 0; i < 8; i++) sv[tid + 256 * i] = wv[tid + 256 * i];
    }
    __syncthreads();
    int tx = tid & 15, ty = tid >> 4;
    int c0 = tx * 4;
    long rowbase = (long)blockIdx.x * 64 + ty * 4;

    long rowc[4];
#pragma unroll
    for (int r = 0; r < 4; r++) {
        long rr = rowbase + r;
        rowc[r] = (rr < N) ? rr : (long)(N - 1);
    }
    unsigned long long acc[4][2];
#pragma unroll
    for (int r = 0; r < 4; r++) { acc[r][0] = 0ull; acc[r][1] = 0ull; }

#pragma unroll 4
    for (int k0 = 0; k0 < 128; k0 += 4) {
        float a_[4][4];
#pragma unroll
        for (int r = 0; r < 4; r++)
            *(float4*)a_[r] = __ldg((const float4*)(g_h1 + (size_t)rowc[r] * 128 + k0));
#pragma unroll
        for (int kk = 0; kk < 4; kk++) {
            int k = k0 + kk;
            ulonglong2 wv = *(const ulonglong2*)&Ws[k * 64 + c0];
#pragma unroll
            for (int r = 0; r < 4; r++) {
                unsigned long long Ar = pack2(a_[r][kk], a_[r][kk]);
                acc[r][0] = fma2(Ar, wv.x, acc[r][0]);
                acc[r][1] = fma2(Ar, wv.y, acc[r][1]);
            }
        }
    }
#pragma unroll
    for (int r = 0; r < 4; r++) {
        long row = rowbase + r;
        if (row >= N) break;
        float o[4];
        unpack2(acc[r][0], o[0], o[1]);
        unpack2(acc[r][1], o[2], o[3]);
        float4 po = make_float4(o[0], o[1], o[2], o[3]);
        *(float4*)(g_p2 + (size_t)row * 64 + c0) = po;
        float dv = g_dinv[row];
        float w = dv * dv;
        po.x *= w; po.y *= w; po.z *= w; po.w *= w;
        *(float4*)(g_agg2 + (size_t)row * 64 + c0) = po;
    }
}

// per-node readout: pAB[n] = (dot(relu(agg2+b2), Wc[:64]), dot(relu(agg2+b2), Wc[64:]))
__global__ void __launch_bounds__(256) k_nodescore(const float* __restrict__ Wc,
                                                   const float* __restrict__ b2, int N) {
    int tid = threadIdx.x;
    int l = tid & 15;
    int row = blockIdx.x * 16 + (tid >> 4);
    if (row >= N) return;
    float4 wa = __ldg((const float4*)Wc + l);
    float4 wb = __ldg((const float4*)Wc + 16 + l);
    float4 b4 = __ldg((const float4*)b2 + l);
    float4 v = ((const float4*)g_agg2)[(size_t)row * 16 + l];
    v.x = fmaxf(v.x + b4.x, 0.f); v.y = fmaxf(v.y + b4.y, 0.f);
    v.z = fmaxf(v.z + b4.z, 0.f); v.w = fmaxf(v.w + b4.w, 0.f);
    float pa = v.x * wa.x + v.y * wa.y + v.z * wa.z + v.w * wa.w;
    float pb = v.x * wb.x + v.y * wb.y + v.z * wb.z + v.w * wb.w;
#pragma unroll
    for (int o = 8; o >= 1; o >>= 1) {
        pa += __shfl_down_sync(0xffffffffu, pa, o, 16);
        pb += __shfl_down_sync(0xffffffffu, pb, o, 16);
    }
    if (l == 0) g_pAB[row] = make_float2(pa, pb);
}

__global__ void __launch_bounds__(256) k_edge(const float* __restrict__ bcp,
                                              float* __restrict__ out, int E) {
    long e = (long)blockIdx.x * 256 + threadIdx.x;
    if (e >= E) return;
    int s = g_src[e], d = g_dst[e];
    float2 ps = __ldg(&g_pAB[s]);
    float2 pd = __ldg(&g_pAB[d]);
    float z = ps.x + pd.y + __ldg(bcp);
    out[e] = 1.0f / (1.0f + __expf(-z));
}

// ---------------- launcher ----------------
extern "C" void kernel_launch(void* const* d_in, const int* in_sizes, int n_in,
                              void* d_out, int out_size) {
    const float* x  = (const float*)d_in[0];
    const void*  ei = d_in[1];
    const float* W1 = (const float*)d_in[2];
    const float* b1 = (const float*)d_in[3];
    const float* W2 = (const float*)d_in[4];
    const float* b2 = (const float*)d_in[5];
    const float* Wc = (const float*)d_in[6];
    const float* bc = (const float*)d_in[7];
    float* out = (float*)d_out;

    int N = in_sizes[0] / 64;
    int E = in_sizes[1] / 2;
    if (N > N_MAX) N = N_MAX;
    if (E > E_MAX) E = E_MAX;

    int eb2  = (E + 31) / 32;
    int nb16 = (N + 15) / 16;
    int gb   = (N + 63) / 64;

    k_deg_init <<<(N + 255) / 256, 256>>>(N);
    k_convert  <<<(E + 255) / 256, 256>>>(ei, E);
    k_selfinit <<<nb16, 256>>>(x, N);
    k_agg      <<<eb2, 256>>>(x, E, 0);
    k_gemm1    <<<gb, 256>>>(W1, b1, N);
    k_gemm2    <<<gb, 256>>>(W2, N);
    k_agg      <<<eb2, 256>>>(x, E, 1);
    k_nodescore<<<nb16, 256>>>(Wc, b2, N);
    k_edge     <<<(E + 255) / 256, 256>>>(bc, out, E);
}

// round 4
// speedup vs baseline: 1.0062x; 1.0062x over previous
#include <cuda_runtime.h>
#include <cuda_bf16.h>

#define N_MAX 100000
#define E_MAX 1000000

// ---------------- device scratch ----------------
__device__ float  g_dinv[N_MAX];
__device__ int    g_src[E_MAX];
__device__ int    g_dst[E_MAX];
__device__ float  g_agg1[(size_t)N_MAX * 64];
__device__ float  g_h1  [(size_t)N_MAX * 128];
__device__ float  g_p2  [(size_t)N_MAX * 64];
__device__ float  g_agg2[(size_t)N_MAX * 64];
__device__ float2 g_pAB [N_MAX];

// ---------------- helpers ----------------
__device__ __forceinline__ void red_add_v4(float* p, float4 v) {
    asm volatile("red.global.add.v4.f32 [%0], {%1, %2, %3, %4};"
                 :: "l"(p), "f"(v.x), "f"(v.y), "f"(v.z), "f"(v.w)
                 : "memory");
}
__device__ __forceinline__ unsigned long long fma2(unsigned long long a,
                                                   unsigned long long b,
                                                   unsigned long long c) {
    unsigned long long d;
    asm("fma.rn.f32x2 %0, %1, %2, %3;" : "=l"(d) : "l"(a), "l"(b), "l"(c));
    return d;
}
__device__ __forceinline__ unsigned long long pack2(float x, float y) {
    unsigned long long d;
    asm("mov.b64 %0, {%1, %2};" : "=l"(d) : "f"(x), "f"(y));
    return d;
}
__device__ __forceinline__ void unpack2(unsigned long long v, float& lo, float& hi) {
    asm("mov.b64 {%0, %1}, %2;" : "=f"(lo), "=f"(hi) : "l"(v));
}

// ---------------- kernels ----------------

__global__ void __launch_bounds__(256) k_deg_init(int N) {
    int i = blockIdx.x * 256 + threadIdx.x;
    if (i < N) g_dinv[i] = 1.0f;
}

__global__ void __launch_bounds__(256) k_convert(const void* __restrict__ ei, int E) {
    long i = (long)blockIdx.x * 256 + threadIdx.x;
    if (i >= E) return;
    const unsigned long long* p64 = (const unsigned long long*)ei;
    bool is64 = true;
#pragma unroll
    for (int j = 0; j < 8; j++) is64 &= (p64[j] < (unsigned long long)N_MAX);
    int s, d;
    if (is64) {
        s = (int)p64[i];
        d = (int)p64[(long)E + i];
    } else {
        const int* p32 = (const int*)ei;
        s = p32[i];
        d = p32[(long)E + i];
    }
    g_src[i] = s;
    g_dst[i] = d;
    atomicAdd(&g_dinv[d], 1.0f);
}

// dinv = rsqrt(deg); agg1[i] = x[i]/deg[i]  (self-loop term)
__global__ void __launch_bounds__(256) k_selfinit(const float* __restrict__ x, int N) {
    int tid = threadIdx.x;
    int l = tid & 15;
    int row = blockIdx.x * 16 + (tid >> 4);
    if (row >= N) return;
    float dv = rsqrtf(g_dinv[row]);
    if (l == 0) g_dinv[row] = dv;
    float w = dv * dv;
    float4 v = __ldg((const float4*)x + (size_t)row * 16 + l);
    v.x *= w; v.y *= w; v.z *= w; v.w *= w;
    ((float4*)g_agg1)[(size_t)row * 16 + l] = v;
}

// Edge aggregation: 2 edges per thread-group for MLP.
__global__ void __launch_bounds__(256) k_agg(const float* __restrict__ xin, int E, int which) {
    int tid = threadIdx.x;
    int l = tid & 15;
    long e0 = (long)blockIdx.x * 32 + (tid >> 4);
    long e1 = e0 + 16;
    const float4* f4 = which ? (const float4*)g_p2 : (const float4*)xin;
    float*        ob = which ? g_agg2 : g_agg1;
    bool v0 = e0 < E, v1 = e1 < E;
    int s0 = 0, d0 = 0, s1 = 0, d1 = 0;
    if (v0) { s0 = g_src[e0]; d0 = g_dst[e0]; }
    if (v1) { s1 = g_src[e1]; d1 = g_dst[e1]; }
    float w0 = 0.f, w1 = 0.f;
    if (v0) w0 = g_dinv[s0] * g_dinv[d0];
    if (v1) w1 = g_dinv[s1] * g_dinv[d1];
    float4 x0 = make_float4(0, 0, 0, 0), x1 = x0;
    if (v0) x0 = __ldg(f4 + (size_t)s0 * 16 + l);
    if (v1) x1 = __ldg(f4 + (size_t)s1 * 16 + l);
    if (v0) {
        x0.x *= w0; x0.y *= w0; x0.z *= w0; x0.w *= w0;
        red_add_v4(ob + (size_t)d0 * 64 + l * 4, x0);
    }
    if (v1) {
        x1.x *= w1; x1.y *= w1; x1.z *= w1; x1.w *= w1;
        red_add_v4(ob + (size_t)d1 * 64 + l * 4, x1);
    }
}

// h1 = relu(agg1 @ W1 + b1)   [N,64]x[64,128]
// block = 64 rows x 128 cols; thread = 4 rows x 8 cols via f32x2.
__global__ void __launch_bounds__(256) k_gemm1(const float* __restrict__ W,
                                               const float* __restrict__ b, int N) {
    __shared__ float Ws[64 * 128];
    int tid = threadIdx.x;
    {
        const float4* wv = (const float4*)W;
        float4* sv = (float4*)Ws;
#pragma unroll
        for (int i = 0; i < 8; i++) sv[tid + 256 * i] = wv[tid + 256 * i];
    }
    __syncthreads();
    int tx = tid & 15, ty = tid >> 4;
    int c0 = tx * 8;
    long rowbase = (long)blockIdx.x * 64 + ty * 4;

    long rowc[4];
#pragma unroll
    for (int r = 0; r < 4; r++) {
        long rr = rowbase + r;
        rowc[r] = (rr < N) ? rr : (long)(N - 1);
    }
    unsigned long long acc[4][4];
    {
        float4 b0 = __ldg((const float4*)(b + c0));
        float4 b1 = __ldg((const float4*)(b + c0 + 4));
#pragma unroll
        for (int r = 0; r < 4; r++) {
            acc[r][0] = pack2(b0.x, b0.y);
            acc[r][1] = pack2(b0.z, b0.w);
            acc[r][2] = pack2(b1.x, b1.y);
            acc[r][3] = pack2(b1.z, b1.w);
        }
    }
#pragma unroll 4
    for (int k0 = 0; k0 < 64; k0 += 4) {
        float a_[4][4];
#pragma unroll
        for (int r = 0; r < 4; r++)
            *(float4*)a_[r] = __ldg((const float4*)(g_agg1 + (size_t)rowc[r] * 64 + k0));
#pragma unroll
        for (int kk = 0; kk < 4; kk++) {
            int k = k0 + kk;
            ulonglong2 wa = *(const ulonglong2*)&Ws[k * 128 + c0];
            ulonglong2 wb = *(const ulonglong2*)&Ws[k * 128 + c0 + 4];
#pragma unroll
            for (int r = 0; r < 4; r++) {
                unsigned long long Ar = pack2(a_[r][kk], a_[r][kk]);
                acc[r][0] = fma2(Ar, wa.x, acc[r][0]);
                acc[r][1] = fma2(Ar, wa.y, acc[r][1]);
                acc[r][2] = fma2(Ar, wb.x, acc[r][2]);
                acc[r][3] = fma2(Ar, wb.y, acc[r][3]);
            }
        }
    }
#pragma unroll
    for (int r = 0; r < 4; r++) {
        long row = rowbase + r;
        if (row >= N) break;
        float o[8];
        unpack2(acc[r][0], o[0], o[1]);
        unpack2(acc[r][1], o[2], o[3]);
        unpack2(acc[r][2], o[4], o[5]);
        unpack2(acc[r][3], o[6], o[7]);
#pragma unroll
        for (int j = 0; j < 8; j++) o[j] = fmaxf(o[j], 0.f);
        float* dst = g_h1 + (size_t)row * 128 + c0;
        *(float4*)dst       = make_float4(o[0], o[1], o[2], o[3]);
        *(float4*)(dst + 4) = make_float4(o[4], o[5], o[6], o[7]);
    }
}

// p2 = h1 @ W2 (no bias); agg2 = p2 * dinv^2 (fused self-loop init)
// block = 64 rows x 64 cols; thread = 4 rows x 4 cols.
__global__ void __launch_bounds__(256) k_gemm2(const float* __restrict__ W, int N) {
    __shared__ float Ws[128 * 64];
    int tid = threadIdx.x;
    {
        const float4* wv = (const float4*)W;
        float4* sv = (float4*)Ws;
#pragma unroll
        for (int i = 0; i < 8; i++) sv[tid + 256 * i] = wv[tid + 256 * i];
    }
    __syncthreads();
    int tx = tid & 15, ty = tid >> 4;
    int c0 = tx * 4;
    long rowbase = (long)blockIdx.x * 64 + ty * 4;

    long rowc[4];
#pragma unroll
    for (int r = 0; r < 4; r++) {
        long rr = rowbase + r;
        rowc[r] = (rr < N) ? rr : (long)(N - 1);
    }
    unsigned long long acc[4][2];
#pragma unroll
    for (int r = 0; r < 4; r++) { acc[r][0] = 0ull; acc[r][1] = 0ull; }

#pragma unroll 4
    for (int k0 = 0; k0 < 128; k0 += 4) {
        float a_[4][4];
#pragma unroll
        for (int r = 0; r < 4; r++)
            *(float4*)a_[r] = __ldg((const float4*)(g_h1 + (size_t)rowc[r] * 128 + k0));
#pragma unroll
        for (int kk = 0; kk < 4; kk++) {
            int k = k0 + kk;
            ulonglong2 wv = *(const ulonglong2*)&Ws[k * 64 + c0];
#pragma unroll
            for (int r = 0; r < 4; r++) {
                unsigned long long Ar = pack2(a_[r][kk], a_[r][kk]);
                acc[r][0] = fma2(Ar, wv.x, acc[r][0]);
                acc[r][1] = fma2(Ar, wv.y, acc[r][1]);
            }
        }
    }
#pragma unroll
    for (int r = 0; r < 4; r++) {
        long row = rowbase + r;
        if (row >= N) break;
        float o[4];
        unpack2(acc[r][0], o[0], o[1]);
        unpack2(acc[r][1], o[2], o[3]);
        float4 po = make_float4(o[0], o[1], o[2], o[3]);
        *(float4*)(g_p2 + (size_t)row * 64 + c0) = po;
        float dv = g_dinv[row];
        float w = dv * dv;
        po.x *= w; po.y *= w; po.z *= w; po.w *= w;
        *(float4*)(g_agg2 + (size_t)row * 64 + c0) = po;
    }
}

// per-node readout: pAB[n] = (dot(relu(agg2+b2), Wc[:64]), dot(relu(agg2+b2), Wc[64:]))
__global__ void __launch_bounds__(256) k_nodescore(const float* __restrict__ Wc,
                                                   const float* __restrict__ b2, int N) {
    int tid = threadIdx.x;
    int l = tid & 15;
    int row = blockIdx.x * 16 + (tid >> 4);
    if (row >= N) return;
    float4 wa = __ldg((const float4*)Wc + l);
    float4 wb = __ldg((const float4*)Wc + 16 + l);
    float4 b4 = __ldg((const float4*)b2 + l);
    float4 v = ((const float4*)g_agg2)[(size_t)row * 16 + l];
    v.x = fmaxf(v.x + b4.x, 0.f); v.y = fmaxf(v.y + b4.y, 0.f);
    v.z = fmaxf(v.z + b4.z, 0.f); v.w = fmaxf(v.w + b4.w, 0.f);
    float pa = v.x * wa.x + v.y * wa.y + v.z * wa.z + v.w * wa.w;
    float pb = v.x * wb.x + v.y * wb.y + v.z * wb.z + v.w * wb.w;
#pragma unroll
    for (int o = 8; o >= 1; o >>= 1) {
        pa += __shfl_down_sync(0xffffffffu, pa, o, 16);
        pb += __shfl_down_sync(0xffffffffu, pb, o, 16);
    }
    if (l == 0) g_pAB[row] = make_float2(pa, pb);
}

__global__ void __launch_bounds__(256) k_edge(const float* __restrict__ bcp,
                                              float* __restrict__ out, int E) {
    long e = (long)blockIdx.x * 256 + threadIdx.x;
    if (e >= E) return;
    int s = g_src[e], d = g_dst[e];
    float2 ps = __ldg(&g_pAB[s]);
    float2 pd = __ldg(&g_pAB[d]);
    float z = ps.x + pd.y + __ldg(bcp);
    out[e] = 1.0f / (1.0f + __expf(-z));
}

// ---------------- launcher ----------------
extern "C" void kernel_launch(void* const* d_in, const int* in_sizes, int n_in,
                              void* d_out, int out_size) {
    const float* x  = (const float*)d_in[0];
    const void*  ei = d_in[1];
    const float* W1 = (const float*)d_in[2];
    const float* b1 = (const float*)d_in[3];
    const float* W2 = (const float*)d_in[4];
    const float* b2 = (const float*)d_in[5];
    const float* Wc = (const float*)d_in[6];
    const float* bc = (const float*)d_in[7];
    float* out = (float*)d_out;

    int N = in_sizes[0] / 64;
    int E = in_sizes[1] / 2;
    if (N > N_MAX) N = N_MAX;
    if (E > E_MAX) E = E_MAX;

    int eb2  = (E + 31) / 32;
    int nb16 = (N + 15) / 16;
    int gb   = (N + 63) / 64;

    k_deg_init <<<(N + 255) / 256, 256>>>(N);
    k_convert  <<<(E + 255) / 256, 256>>>(ei, E);
    k_selfinit <<<nb16, 256>>>(x, N);
    k_agg      <<<eb2, 256>>>(x, E, 0);
    k_gemm1    <<<gb, 256>>>(W1, b1, N);
    k_gemm2    <<<gb, 256>>>(W2, N);
    k_agg      <<<eb2, 256>>>(x, E, 1);
    k_nodescore<<<nb16, 256>>>(Wc, b2, N);
    k_edge     <<<(E + 255) / 256, 256>>>(bc, out, E);
}